// round 9
// baseline (speedup 1.0000x reference)
#include <cuda_runtime.h>
#include <cuda_bf16.h>

#define N_NODES_C 200000
#define N_EDGES_C 3200000
#define N_GRAPHS_C 1024

// ---------------- static device scratch (no allocs allowed) ----------------
__device__ __align__(16) float g_bufA[(size_t)N_NODES_C * 64];
__device__ __align__(16) float g_bufB[(size_t)N_NODES_C * 64];
__device__ __align__(16) float g_bufC[(size_t)N_NODES_C * 32];
__device__ __align__(16) float g_bufD[(size_t)N_NODES_C * 64];
__device__ __align__(16) int4  g_meta[N_EDGES_C];          // {src, dst, norm_bits, pad}
__device__ __align__(16) int   g_deg[N_NODES_C];
__device__ __align__(16) float g_dinv[N_NODES_C];
__device__ __align__(16) float g_gmax[N_GRAPHS_C * 32];
__device__ __align__(16) float g_gsum[N_GRAPHS_C * 32];
__device__ __align__(16) float g_gcnt[N_GRAPHS_C];

// ---------------- helpers ----------------
__device__ __forceinline__ void red_add_v4(float* addr, float4 v) {
    asm volatile("red.global.add.v4.f32 [%0], {%1, %2, %3, %4};"
                 :: "l"(addr), "f"(v.x), "f"(v.y), "f"(v.z), "f"(v.w)
                 : "memory");
}

__device__ __forceinline__ unsigned long long fma2(unsigned long long a,
                                                   unsigned long long b,
                                                   unsigned long long c) {
    unsigned long long d;
    asm("fma.rn.f32x2 %0, %1, %2, %3;" : "=l"(d) : "l"(a), "l"(b), "l"(c));
    return d;
}

__device__ __forceinline__ unsigned long long pack2(float x) {
    unsigned long long r;
    asm("mov.b64 %0, {%1, %1};" : "=l"(r) : "r"(__float_as_uint(x)));
    return r;
}

// ---------------- degree (vectorized index loads) ----------------
__global__ void deg_kernel(const int* __restrict__ dst, int* __restrict__ deg, int E) {
    int t = blockIdx.x * blockDim.x + threadIdx.x;
    int e0 = t * 4;
    if (e0 >= E) return;
    if (e0 + 3 < E) {
        int4 d4 = *(const int4*)(dst + e0);
        atomicAdd(&deg[d4.x], 1);
        atomicAdd(&deg[d4.y], 1);
        atomicAdd(&deg[d4.z], 1);
        atomicAdd(&deg[d4.w], 1);
    } else {
        for (int k = 0; e0 + k < E; k++) atomicAdd(&deg[dst[e0 + k]], 1);
    }
}

__global__ void dinv_kernel(const int* __restrict__ deg, float* __restrict__ dinv, int N) {
    int i = blockIdx.x * blockDim.x + threadIdx.x;
    if (i < N) dinv[i] = rsqrtf((float)(deg[i] + 1));  // +1 self-loop
}

// ---------------- prep (generic): act/init writer ----------------
// agg[i][c] = dinv[i]^2 * act(in[i][c]);  optionally write act(in) to actout
template<int C, bool RELU_IN, bool WRITEACT>
__global__ void prep_kernel(const float* __restrict__ in, float* __restrict__ actout,
                            float* __restrict__ agg, const float* __restrict__ dinv, int N) {
    int node = blockIdx.x * blockDim.x + threadIdx.x;
    if (node >= N) return;
    float di = dinv[node];
    float s = di * di;
    size_t base = (size_t)node * C;
    #pragma unroll
    for (int j = 0; j < C / 4; j++) {
        float4 v = *(const float4*)(in + base + j * 4);
        if (RELU_IN) {
            v.x = fmaxf(v.x, 0.f); v.y = fmaxf(v.y, 0.f);
            v.z = fmaxf(v.z, 0.f); v.w = fmaxf(v.w, 0.f);
        }
        if (WRITEACT) *(float4*)(actout + base + j * 4) = v;
        float4 a; a.x = s * v.x; a.y = s * v.y; a.z = s * v.z; a.w = s * v.w;
        *(float4*)(agg + base + j * 4) = a;
    }
}

// ---------------- layer-0 edge pass: also builds edge meta {s,d,norm} ----------------
__global__ void edge0_kernel(const float* __restrict__ x, float* __restrict__ agg,
                             const int* __restrict__ src, const int* __restrict__ dst,
                             const float* __restrict__ dinv, int4* __restrict__ meta, int E) {
    int t = blockIdx.x * blockDim.x + threadIdx.x;
    int e0 = t * 4;
    if (e0 >= E) return;
    int ss[4], dd[4];
    int n = (e0 + 3 < E) ? 4 : (E - e0);
    if (n == 4) {
        int4 s4 = *(const int4*)(src + e0);
        int4 d4 = *(const int4*)(dst + e0);
        ss[0] = s4.x; ss[1] = s4.y; ss[2] = s4.z; ss[3] = s4.w;
        dd[0] = d4.x; dd[1] = d4.y; dd[2] = d4.z; dd[3] = d4.w;
    } else {
        for (int k = 0; k < n; k++) { ss[k] = src[e0 + k]; dd[k] = dst[e0 + k]; }
    }
    #pragma unroll 4
    for (int k = 0; k < n; k++) {
        int s = ss[k], d = dd[k];
        float nrm = dinv[s] * dinv[d];
        meta[e0 + k] = make_int4(s, d, __float_as_int(nrm), 0);
        float4 v0 = *(const float4*)(x + (size_t)s * 8);
        float4 v1 = *(const float4*)(x + (size_t)s * 8 + 4);
        v0.x *= nrm; v0.y *= nrm; v0.z *= nrm; v0.w *= nrm;
        v1.x *= nrm; v1.y *= nrm; v1.z *= nrm; v1.w *= nrm;
        red_add_v4(agg + (size_t)d * 8, v0);
        red_add_v4(agg + (size_t)d * 8 + 4, v1);
    }
}

// ---------------- meta-based edge scatter: thread per edge ----------------
template<int C>
__global__ void edgeM_kernel(const float* __restrict__ t, float* __restrict__ agg,
                             const int4* __restrict__ meta, int E) {
    int e = blockIdx.x * blockDim.x + threadIdx.x;
    if (e >= E) return;
    int4 m = meta[e];
    int s = m.x, d = m.y;
    float nrm = __int_as_float(m.z);
    const float4* __restrict__ rowp = (const float4*)(t + (size_t)s * C);
    float4 v[C / 4];
    #pragma unroll
    for (int j = 0; j < C / 4; j++) v[j] = rowp[j];
    float* outp = agg + (size_t)d * C;
    #pragma unroll
    for (int j = 0; j < C / 4; j++) {
        float4 w = v[j];
        w.x *= nrm; w.y *= nrm; w.z *= nrm; w.w *= nrm;
        red_add_v4(outp + j * 4, w);
    }
}

// ---------------- GEMM: out[i] = act(in[i] @ W (+ b)); optional init output ----------------
// ACT: 0=none, 1=tanh, 2=relu.  WINIT: also write init_out = dinv^2*out (+init_b)
// NOTE: in / out / init_out MUST be distinct buffers (no in-place).
template<int IN, int OUT, int ACT, bool HASB, bool WINIT, bool INITB>
__global__ void gemm_kernel(const float* __restrict__ in, const float* __restrict__ W,
                            const float* __restrict__ b, float* __restrict__ out,
                            float* __restrict__ init_out, const float* __restrict__ dinv,
                            const float* __restrict__ init_b, int N) {
    __shared__ __align__(16) float Ws[IN * OUT];
    __shared__ __align__(16) float bs[OUT];
    __shared__ __align__(16) float ibs[OUT];
    for (int i = threadIdx.x; i < IN * OUT; i += blockDim.x) Ws[i] = W[i];
    if (HASB) for (int i = threadIdx.x; i < OUT; i += blockDim.x) bs[i] = b[i];
    if (INITB) for (int i = threadIdx.x; i < OUT; i += blockDim.x) ibs[i] = init_b[i];
    __syncthreads();

    int node = blockIdx.x * blockDim.x + threadIdx.x;
    if (node >= N) return;
    const float* row = in + (size_t)node * IN;

    unsigned long long acc[OUT / 2];
    #pragma unroll
    for (int j = 0; j < OUT / 2; j++) {
        if (HASB) {
            float2 bb = *(const float2*)&bs[2 * j];
            unsigned long long p;
            asm("mov.b64 %0, {%1, %2};" : "=l"(p)
                : "r"(__float_as_uint(bb.x)), "r"(__float_as_uint(bb.y)));
            acc[j] = p;
        } else {
            acc[j] = 0ULL;
        }
    }

    #pragma unroll 4
    for (int k = 0; k < IN; k++) {
        unsigned long long xk2 = pack2(row[k]);
        const unsigned long long* wrow = (const unsigned long long*)&Ws[k * OUT];
        #pragma unroll
        for (int j = 0; j < OUT / 2; j++)
            acc[j] = fma2(xk2, wrow[j], acc[j]);
    }

    float sc = 0.f;
    if (WINIT) { float di = dinv[node]; sc = di * di; }

    float* o = out + (size_t)node * OUT;
    float* io = WINIT ? (init_out + (size_t)node * OUT) : nullptr;
    #pragma unroll
    for (int j = 0; j < OUT / 2; j++) {
        float2 v;
        unsigned int lo, hi;
        asm("mov.b64 {%0, %1}, %2;" : "=r"(lo), "=r"(hi) : "l"(acc[j]));
        v.x = __uint_as_float(lo); v.y = __uint_as_float(hi);
        if (ACT == 1) { v.x = tanhf(v.x); v.y = tanhf(v.y); }
        if (ACT == 2) { v.x = fmaxf(v.x, 0.f); v.y = fmaxf(v.y, 0.f); }
        *(float2*)(o + 2 * j) = v;
        if (WINIT) {
            float2 iv;
            if (INITB) {
                iv.x = fmaf(sc, v.x, ibs[2 * j]);
                iv.y = fmaf(sc, v.y, ibs[2 * j + 1]);
            } else {
                iv.x = sc * v.x; iv.y = sc * v.y;
            }
            *(float2*)(io + 2 * j) = iv;
        }
    }
}

// ---------------- pooling: per-graph max + sum + count over 32 channels ----------------
__global__ void pool_kernel(const float* __restrict__ h, const int* __restrict__ batch,
                            float* __restrict__ gmax, float* __restrict__ gsum,
                            float* __restrict__ gcnt, int N) {
    int gid = blockIdx.x * blockDim.x + threadIdx.x;
    int node = gid / 8;
    int j = gid % 8;
    if (node >= N) return;
    float4 v = *(const float4*)(h + (size_t)node * 32 + j * 4);
    int g = batch[node];
    int base = g * 32 + j * 4;
    // h is post-ReLU (>=0) so int compare == float compare; gmax init = 0
    atomicMax((int*)gmax + base + 0, __float_as_int(v.x));
    atomicMax((int*)gmax + base + 1, __float_as_int(v.y));
    atomicMax((int*)gmax + base + 2, __float_as_int(v.z));
    atomicMax((int*)gmax + base + 3, __float_as_int(v.w));
    red_add_v4(gsum + base, v);
    if (j == 0) atomicAdd(&gcnt[g], 1.0f);
}

// ---------------- final linear: out[g][o] = [gmax|gmean] @ Wout + bout ----------------
__global__ void out_kernel(const float* __restrict__ gmax, const float* __restrict__ gsum,
                           const float* __restrict__ gcnt, const float* __restrict__ Wout,
                           const float* __restrict__ bout, float* __restrict__ out) {
    int gid = blockIdx.x * blockDim.x + threadIdx.x;
    if (gid >= N_GRAPHS_C * 10) return;
    int g = gid / 10, o = gid % 10;
    float inv = 1.0f / fmaxf(gcnt[g], 1.0f);
    float acc = bout[o];
    #pragma unroll
    for (int k = 0; k < 32; k++) acc += gmax[g * 32 + k] * Wout[k * 10 + o];
    #pragma unroll
    for (int k = 0; k < 32; k++) acc += gsum[g * 32 + k] * inv * Wout[(32 + k) * 10 + o];
    out[gid] = acc;
}

// ---------------- launch ----------------
static inline int cdiv(long long a, int b) { return (int)((a + b - 1) / b); }

extern "C" void kernel_launch(void* const* d_in, const int* in_sizes, int n_in,
                              void* d_out, int out_size) {
    const float* x     = (const float*)d_in[0];
    const int*   ei    = (const int*)d_in[1];    // int32 (JAX x64 disabled)
    const int*   batch = (const int*)d_in[2];    // int32
    const float* W0 = (const float*)d_in[3];
    const float* b0 = (const float*)d_in[4];
    const float* W1 = (const float*)d_in[5];
    const float* b1 = (const float*)d_in[6];
    const float* W2 = (const float*)d_in[7];
    const float* b2 = (const float*)d_in[8];
    const float* W3 = (const float*)d_in[9];
    const float* b3 = (const float*)d_in[10];
    const float* Wout = (const float*)d_in[11];
    const float* bout = (const float*)d_in[12];

    int N = in_sizes[0] / 8;
    int E = in_sizes[1] / 2;
    const int* src = ei;
    const int* dst = ei + E;

    float *bufA, *bufB, *bufC, *bufD, *dinv, *gmax, *gsum, *gcnt;
    int *deg; int4 *meta;
    cudaGetSymbolAddress((void**)&bufA, g_bufA);
    cudaGetSymbolAddress((void**)&bufB, g_bufB);
    cudaGetSymbolAddress((void**)&bufC, g_bufC);
    cudaGetSymbolAddress((void**)&bufD, g_bufD);
    cudaGetSymbolAddress((void**)&meta, g_meta);
    cudaGetSymbolAddress((void**)&deg,  g_deg);
    cudaGetSymbolAddress((void**)&dinv, g_dinv);
    cudaGetSymbolAddress((void**)&gmax, g_gmax);
    cudaGetSymbolAddress((void**)&gsum, g_gsum);
    cudaGetSymbolAddress((void**)&gcnt, g_gcnt);

    const int B = 256;

    cudaMemsetAsync(deg,  0, (size_t)N * sizeof(int));
    cudaMemsetAsync(gmax, 0, (size_t)N_GRAPHS_C * 32 * sizeof(float));
    cudaMemsetAsync(gsum, 0, (size_t)N_GRAPHS_C * 32 * sizeof(float));
    cudaMemsetAsync(gcnt, 0, (size_t)N_GRAPHS_C * sizeof(float));

    deg_kernel<<<cdiv(cdiv(E, 4), B), B>>>(dst, deg, E);
    dinv_kernel<<<cdiv(N, B), B>>>(deg, dinv, N);

    // Layer 0: aggregate at C=8 (AGG(X W) == (AGG X) W); edge0 also builds meta.
    prep_kernel<8, false, false><<<cdiv(N, B), B>>>(x, nullptr, bufA, dinv, N);
    edge0_kernel<<<cdiv(cdiv(E, 4), B), B>>>(x, bufA, src, dst, dinv, meta, E);
    // gemm0: h1 = tanh(agg0@W0+b0) -> bufB; init agg1 = dinv^2*h1 -> bufD  (A,B,D distinct)
    gemm_kernel<8, 64, 1, true, true, false><<<cdiv(N, B), B>>>(bufA, W0, b0, bufB, bufD, dinv, nullptr, N);

    // Layer 1: edge at C=64 (gather bufB, red bufD), gemm1: bufD -> h2 in bufA
    edgeM_kernel<64><<<cdiv(E, B), B>>>(bufB, bufD, meta, E);
    gemm_kernel<64, 64, 2, true, false, false><<<cdiv(N, B), B>>>(bufD, W1, b1, bufA, nullptr, nullptr, nullptr, N);

    // Layer 2: gemm2 (bufA -> t2=bufC; init agg2 = dinv^2*t2 + b2 -> bufB[32-wide])
    gemm_kernel<64, 32, 0, false, true, true><<<cdiv(N, B), B>>>(bufA, W2, nullptr, bufC, bufB, dinv, b2, N);
    edgeM_kernel<32><<<cdiv(E, B), B>>>(bufC, bufB, meta, E);  // agg2 in bufB

    // Layer 3: h3 = relu(agg2:bufB) -> bufC; init agg3 = dinv^2*h3 -> bufD[32-wide]
    prep_kernel<32, true, true><<<cdiv(N, B), B>>>(bufB, bufC, bufD, dinv, N);
    edgeM_kernel<32><<<cdiv(E, B), B>>>(bufC, bufD, meta, E);  // agg3 in bufD
    gemm_kernel<32, 32, 2, true, false, false><<<cdiv(N, B), B>>>(bufD, W3, b3, bufA, nullptr, nullptr, nullptr, N);  // h4 in bufA

    // Pooling + output head
    pool_kernel<<<cdiv((long long)N * 8, B), B>>>(bufA, batch, gmax, gsum, gcnt, N);
    out_kernel<<<cdiv(N_GRAPHS_C * 10, B), B>>>(gmax, gsum, gcnt, Wout, bout, (float*)d_out);
}

// round 11
// speedup vs baseline: 2.0054x; 2.0054x over previous
#include <cuda_runtime.h>
#include <cuda_bf16.h>

#define N_NODES_C 200000
#define N_EDGES_C 3200000
#define N_GRAPHS_C 1024
#define SCAN_B 256
#define MAX_BLOCKS_SCAN 1024

// ---------------- static device scratch (no allocs allowed) ----------------
__device__ __align__(16) float g_bufA[(size_t)N_NODES_C * 64];
__device__ __align__(16) float g_bufB[(size_t)N_NODES_C * 64];
__device__ __align__(16) float g_bufC[(size_t)N_NODES_C * 32];
__device__ __align__(16) float g_bufD[(size_t)N_NODES_C * 64];
__device__ __align__(16) int2  g_csr[N_EDGES_C];          // {src, norm_bits}
__device__ __align__(16) int   g_deg[N_NODES_C];
__device__ __align__(16) int   g_incl[N_NODES_C];
__device__ __align__(16) int   g_rowstart[N_NODES_C];
__device__ __align__(16) int   g_cursor[N_NODES_C];
__device__ __align__(16) int   g_partials[MAX_BLOCKS_SCAN];
__device__ __align__(16) float g_dinv[N_NODES_C];
__device__ __align__(16) float g_gmax[N_GRAPHS_C * 32];
__device__ __align__(16) float g_gsum[N_GRAPHS_C * 32];
__device__ __align__(16) float g_gcnt[N_GRAPHS_C];

// ---------------- helpers ----------------
__device__ __forceinline__ void red_add_v4(float* addr, float4 v) {
    asm volatile("red.global.add.v4.f32 [%0], {%1, %2, %3, %4};"
                 :: "l"(addr), "f"(v.x), "f"(v.y), "f"(v.z), "f"(v.w)
                 : "memory");
}

__device__ __forceinline__ unsigned long long fma2(unsigned long long a,
                                                   unsigned long long b,
                                                   unsigned long long c) {
    unsigned long long d;
    asm("fma.rn.f32x2 %0, %1, %2, %3;" : "=l"(d) : "l"(a), "l"(b), "l"(c));
    return d;
}

__device__ __forceinline__ unsigned long long pack2(float x) {
    unsigned long long r;
    asm("mov.b64 %0, {%1, %1};" : "=l"(r) : "r"(__float_as_uint(x)));
    return r;
}

// ---------------- degree ----------------
__global__ void deg_kernel(const int* __restrict__ dst, int* __restrict__ deg, int E) {
    int t = blockIdx.x * blockDim.x + threadIdx.x;
    int e0 = t * 4;
    if (e0 >= E) return;
    if (e0 + 3 < E) {
        int4 d4 = *(const int4*)(dst + e0);
        atomicAdd(&deg[d4.x], 1);
        atomicAdd(&deg[d4.y], 1);
        atomicAdd(&deg[d4.z], 1);
        atomicAdd(&deg[d4.w], 1);
    } else {
        for (int k = 0; e0 + k < E; k++) atomicAdd(&deg[dst[e0 + k]], 1);
    }
}

__global__ void dinv_kernel(const int* __restrict__ deg, float* __restrict__ dinv, int N) {
    int i = blockIdx.x * blockDim.x + threadIdx.x;
    if (i < N) dinv[i] = rsqrtf((float)(deg[i] + 1));  // +1 self-loop
}

// ---------------- 3-phase exclusive scan of deg -> rowstart (+cursor copy) --------
__global__ void scan_block_kernel(const int* __restrict__ deg, int* __restrict__ incl,
                                  int* __restrict__ partials, int N) {
    __shared__ int sh[SCAN_B];
    int tid = threadIdx.x;
    int i = blockIdx.x * SCAN_B + tid;
    int v = (i < N) ? deg[i] : 0;
    sh[tid] = v;
    __syncthreads();
    #pragma unroll
    for (int off = 1; off < SCAN_B; off <<= 1) {
        int t = (tid >= off) ? sh[tid - off] : 0;
        __syncthreads();
        sh[tid] += t;
        __syncthreads();
    }
    if (i < N) incl[i] = sh[tid];
    if (tid == SCAN_B - 1) partials[blockIdx.x] = sh[tid];
}

__global__ void scan_partials_kernel(int* __restrict__ partials, int NB) {
    __shared__ int sh[MAX_BLOCKS_SCAN];
    int tid = threadIdx.x;
    sh[tid] = (tid < NB) ? partials[tid] : 0;
    __syncthreads();
    #pragma unroll
    for (int off = 1; off < MAX_BLOCKS_SCAN; off <<= 1) {
        int t = (tid >= off) ? sh[tid - off] : 0;
        __syncthreads();
        sh[tid] += t;
        __syncthreads();
    }
    if (tid < NB) partials[tid] = sh[tid];
}

__global__ void scan_final_kernel(const int* __restrict__ incl, const int* __restrict__ deg,
                                  const int* __restrict__ partials,
                                  int* __restrict__ rowstart, int* __restrict__ cursor, int N) {
    int i = blockIdx.x * SCAN_B + threadIdx.x;
    if (i >= N) return;
    int off = (blockIdx.x > 0) ? partials[blockIdx.x - 1] : 0;
    int rs = incl[i] - deg[i] + off;  // exclusive scan
    rowstart[i] = rs;
    cursor[i] = rs;
}

// ---------------- CSR fill: csr[pos] = {src, norm} grouped by dst ----------------
__global__ void fill_kernel(const int* __restrict__ src, const int* __restrict__ dst,
                            const float* __restrict__ dinv, int* __restrict__ cursor,
                            int2* __restrict__ csr, int E) {
    int e = blockIdx.x * blockDim.x + threadIdx.x;
    if (e >= E) return;
    int s = src[e];
    int d = dst[e];
    float nrm = dinv[s] * dinv[d];
    int pos = atomicAdd(&cursor[d], 1);
    csr[pos] = make_int2(s, __float_as_int(nrm));
}

// ---------------- gather aggregation: chunk-parallel (C/4 threads per node) -------
// agg[i] = sum_{e in-edges} nrm_e * act(t[src_e]) + dinv[i]^2 * act(t[i]) (+ b)
// SRC_RELU: apply relu to every gathered row (including self).
template<int C, bool SRC_RELU, bool ADDB>
__global__ void gather_kernel(const float* __restrict__ t, float* __restrict__ agg,
                              const int2* __restrict__ csr, const int* __restrict__ rowstart,
                              const int* __restrict__ deg, const float* __restrict__ dinv,
                              const float* __restrict__ b, int N) {
    const int TPN = C / 4;
    int gid = blockIdx.x * blockDim.x + threadIdx.x;
    int node = gid / TPN;
    int j = gid % TPN;
    if (node >= N) return;

    int start = rowstart[node];
    int cnt = deg[node];
    float di = dinv[node];
    float s2 = di * di;

    // self term (coalesced read)
    float4 self = *(const float4*)(t + (size_t)node * C + j * 4);
    if (SRC_RELU) {
        self.x = fmaxf(self.x, 0.f); self.y = fmaxf(self.y, 0.f);
        self.z = fmaxf(self.z, 0.f); self.w = fmaxf(self.w, 0.f);
    }
    float4 acc;
    if (ADDB) {
        acc.x = fmaf(s2, self.x, b[j * 4 + 0]);
        acc.y = fmaf(s2, self.y, b[j * 4 + 1]);
        acc.z = fmaf(s2, self.z, b[j * 4 + 2]);
        acc.w = fmaf(s2, self.w, b[j * 4 + 3]);
    } else {
        acc.x = s2 * self.x; acc.y = s2 * self.y;
        acc.z = s2 * self.z; acc.w = s2 * self.w;
    }

    int k = 0;
    for (; k + 2 <= cnt; k += 2) {
        int2 e0 = csr[start + k];
        int2 e1 = csr[start + k + 1];
        float4 v0 = *(const float4*)(t + (size_t)e0.x * C + j * 4);
        float4 v1 = *(const float4*)(t + (size_t)e1.x * C + j * 4);
        float n0 = __int_as_float(e0.y);
        float n1 = __int_as_float(e1.y);
        if (SRC_RELU) {
            v0.x = fmaxf(v0.x, 0.f); v0.y = fmaxf(v0.y, 0.f);
            v0.z = fmaxf(v0.z, 0.f); v0.w = fmaxf(v0.w, 0.f);
            v1.x = fmaxf(v1.x, 0.f); v1.y = fmaxf(v1.y, 0.f);
            v1.z = fmaxf(v1.z, 0.f); v1.w = fmaxf(v1.w, 0.f);
        }
        acc.x = fmaf(n0, v0.x, acc.x); acc.y = fmaf(n0, v0.y, acc.y);
        acc.z = fmaf(n0, v0.z, acc.z); acc.w = fmaf(n0, v0.w, acc.w);
        acc.x = fmaf(n1, v1.x, acc.x); acc.y = fmaf(n1, v1.y, acc.y);
        acc.z = fmaf(n1, v1.z, acc.z); acc.w = fmaf(n1, v1.w, acc.w);
    }
    if (k < cnt) {
        int2 e0 = csr[start + k];
        float4 v0 = *(const float4*)(t + (size_t)e0.x * C + j * 4);
        float n0 = __int_as_float(e0.y);
        if (SRC_RELU) {
            v0.x = fmaxf(v0.x, 0.f); v0.y = fmaxf(v0.y, 0.f);
            v0.z = fmaxf(v0.z, 0.f); v0.w = fmaxf(v0.w, 0.f);
        }
        acc.x = fmaf(n0, v0.x, acc.x); acc.y = fmaf(n0, v0.y, acc.y);
        acc.z = fmaf(n0, v0.z, acc.z); acc.w = fmaf(n0, v0.w, acc.w);
    }

    *(float4*)(agg + (size_t)node * C + j * 4) = acc;
}

// ---------------- GEMM: out[i] = act(in[i] @ W (+ b)) ----------------
// ACT: 0=none, 1=tanh, 2=relu.  in != out.
template<int IN, int OUT, int ACT, bool HASB>
__global__ void gemm_kernel(const float* __restrict__ in, const float* __restrict__ W,
                            const float* __restrict__ b, float* __restrict__ out, int N) {
    __shared__ __align__(16) float Ws[IN * OUT];
    __shared__ __align__(16) float bs[OUT];
    for (int i = threadIdx.x; i < IN * OUT; i += blockDim.x) Ws[i] = W[i];
    if (HASB) for (int i = threadIdx.x; i < OUT; i += blockDim.x) bs[i] = b[i];
    __syncthreads();

    int node = blockIdx.x * blockDim.x + threadIdx.x;
    if (node >= N) return;
    const float* row = in + (size_t)node * IN;

    unsigned long long acc[OUT / 2];
    #pragma unroll
    for (int j = 0; j < OUT / 2; j++) {
        if (HASB) {
            float2 bb = *(const float2*)&bs[2 * j];
            unsigned long long p;
            asm("mov.b64 %0, {%1, %2};" : "=l"(p)
                : "r"(__float_as_uint(bb.x)), "r"(__float_as_uint(bb.y)));
            acc[j] = p;
        } else {
            acc[j] = 0ULL;
        }
    }

    #pragma unroll 4
    for (int k = 0; k < IN; k++) {
        unsigned long long xk2 = pack2(row[k]);
        const unsigned long long* wrow = (const unsigned long long*)&Ws[k * OUT];
        #pragma unroll
        for (int j = 0; j < OUT / 2; j++)
            acc[j] = fma2(xk2, wrow[j], acc[j]);
    }

    float* o = out + (size_t)node * OUT;
    #pragma unroll
    for (int j = 0; j < OUT / 2; j++) {
        float2 v;
        unsigned int lo, hi;
        asm("mov.b64 {%0, %1}, %2;" : "=r"(lo), "=r"(hi) : "l"(acc[j]));
        v.x = __uint_as_float(lo); v.y = __uint_as_float(hi);
        if (ACT == 1) { v.x = tanhf(v.x); v.y = tanhf(v.y); }
        if (ACT == 2) { v.x = fmaxf(v.x, 0.f); v.y = fmaxf(v.y, 0.f); }
        *(float2*)(o + 2 * j) = v;
    }
}

// ---------------- pooling ----------------
__global__ void pool_kernel(const float* __restrict__ h, const int* __restrict__ batch,
                            float* __restrict__ gmax, float* __restrict__ gsum,
                            float* __restrict__ gcnt, int N) {
    int gid = blockIdx.x * blockDim.x + threadIdx.x;
    int node = gid / 8;
    int j = gid % 8;
    if (node >= N) return;
    float4 v = *(const float4*)(h + (size_t)node * 32 + j * 4);
    int g = batch[node];
    int base = g * 32 + j * 4;
    // h is post-ReLU (>=0) so int compare == float compare; gmax init = 0
    atomicMax((int*)gmax + base + 0, __float_as_int(v.x));
    atomicMax((int*)gmax + base + 1, __float_as_int(v.y));
    atomicMax((int*)gmax + base + 2, __float_as_int(v.z));
    atomicMax((int*)gmax + base + 3, __float_as_int(v.w));
    red_add_v4(gsum + base, v);
    if (j == 0) atomicAdd(&gcnt[g], 1.0f);
}

// ---------------- final linear ----------------
__global__ void out_kernel(const float* __restrict__ gmax, const float* __restrict__ gsum,
                           const float* __restrict__ gcnt, const float* __restrict__ Wout,
                           const float* __restrict__ bout, float* __restrict__ out) {
    int gid = blockIdx.x * blockDim.x + threadIdx.x;
    if (gid >= N_GRAPHS_C * 10) return;
    int g = gid / 10, o = gid % 10;
    float inv = 1.0f / fmaxf(gcnt[g], 1.0f);
    float acc = bout[o];
    #pragma unroll
    for (int k = 0; k < 32; k++) acc += gmax[g * 32 + k] * Wout[k * 10 + o];
    #pragma unroll
    for (int k = 0; k < 32; k++) acc += gsum[g * 32 + k] * inv * Wout[(32 + k) * 10 + o];
    out[gid] = acc;
}

// ---------------- launch ----------------
static inline int cdiv(long long a, int b) { return (int)((a + b - 1) / b); }

extern "C" void kernel_launch(void* const* d_in, const int* in_sizes, int n_in,
                              void* d_out, int out_size) {
    const float* x     = (const float*)d_in[0];
    const int*   ei    = (const int*)d_in[1];    // int32 (JAX x64 disabled)
    const int*   batch = (const int*)d_in[2];    // int32
    const float* W0 = (const float*)d_in[3];
    const float* b0 = (const float*)d_in[4];
    const float* W1 = (const float*)d_in[5];
    const float* b1 = (const float*)d_in[6];
    const float* W2 = (const float*)d_in[7];
    const float* b2 = (const float*)d_in[8];
    const float* W3 = (const float*)d_in[9];
    const float* b3 = (const float*)d_in[10];
    const float* Wout = (const float*)d_in[11];
    const float* bout = (const float*)d_in[12];

    int N = in_sizes[0] / 8;
    int E = in_sizes[1] / 2;
    const int* src = ei;
    const int* dst = ei + E;

    float *bufA, *bufB, *bufC, *bufD, *dinv, *gmax, *gsum, *gcnt;
    int *deg, *incl, *rowstart, *cursor, *partials; int2 *csr;
    cudaGetSymbolAddress((void**)&bufA, g_bufA);
    cudaGetSymbolAddress((void**)&bufB, g_bufB);
    cudaGetSymbolAddress((void**)&bufC, g_bufC);
    cudaGetSymbolAddress((void**)&bufD, g_bufD);
    cudaGetSymbolAddress((void**)&csr,  g_csr);
    cudaGetSymbolAddress((void**)&deg,  g_deg);
    cudaGetSymbolAddress((void**)&incl, g_incl);
    cudaGetSymbolAddress((void**)&rowstart, g_rowstart);
    cudaGetSymbolAddress((void**)&cursor,   g_cursor);
    cudaGetSymbolAddress((void**)&partials, g_partials);
    cudaGetSymbolAddress((void**)&dinv, g_dinv);
    cudaGetSymbolAddress((void**)&gmax, g_gmax);
    cudaGetSymbolAddress((void**)&gsum, g_gsum);
    cudaGetSymbolAddress((void**)&gcnt, g_gcnt);

    const int B = 256;
    int NB = cdiv(N, SCAN_B);  // 782 <= 1024

    cudaMemsetAsync(deg,  0, (size_t)N * sizeof(int));
    cudaMemsetAsync(gmax, 0, (size_t)N_GRAPHS_C * 32 * sizeof(float));
    cudaMemsetAsync(gsum, 0, (size_t)N_GRAPHS_C * 32 * sizeof(float));
    cudaMemsetAsync(gcnt, 0, (size_t)N_GRAPHS_C * sizeof(float));

    // ---- graph preprocessing: deg, dinv, CSR ----
    deg_kernel<<<cdiv(cdiv(E, 4), B), B>>>(dst, deg, E);
    dinv_kernel<<<cdiv(N, B), B>>>(deg, dinv, N);
    scan_block_kernel<<<NB, SCAN_B>>>(deg, incl, partials, N);
    scan_partials_kernel<<<1, MAX_BLOCKS_SCAN>>>(partials, NB);
    scan_final_kernel<<<NB, SCAN_B>>>(incl, deg, partials, rowstart, cursor, N);
    fill_kernel<<<cdiv(E, B), B>>>(src, dst, dinv, cursor, csr, E);

    // ---- layer 0: aggregate at C=8 (AGG(X W) == (AGG X) W), then 8->64 tanh ----
    gather_kernel<8, false, false><<<cdiv((long long)N * 2, B), B>>>(x, bufA, csr, rowstart, deg, dinv, nullptr, N);
    gemm_kernel<8, 64, 1, true><<<cdiv(N, B), B>>>(bufA, W0, b0, bufB, N);        // h1 -> bufB

    // ---- layer 1: aggregate C=64, 64->64 relu ----
    gather_kernel<64, false, false><<<cdiv((long long)N * 16, B), B>>>(bufB, bufD, csr, rowstart, deg, dinv, nullptr, N);
    gemm_kernel<64, 64, 2, true><<<cdiv(N, B), B>>>(bufD, W1, b1, bufA, N);       // h2 -> bufA

    // ---- layer 2: GEMM first (64->32, no bias), aggregate C=32 with +b2 ----
    gemm_kernel<64, 32, 0, false><<<cdiv(N, B), B>>>(bufA, W2, nullptr, bufC, N); // t2 -> bufC
    gather_kernel<32, false, true><<<cdiv((long long)N * 8, B), B>>>(bufC, bufB, csr, rowstart, deg, dinv, b2, N);  // agg2(+b2) -> bufB

    // ---- layer 3: aggregate C=32 with on-the-fly relu of agg2, then 32->32 relu ----
    gather_kernel<32, true, false><<<cdiv((long long)N * 8, B), B>>>(bufB, bufD, csr, rowstart, deg, dinv, nullptr, N);  // agg3 -> bufD
    gemm_kernel<32, 32, 2, true><<<cdiv(N, B), B>>>(bufD, W3, b3, bufA, N);       // h4 -> bufA

    // ---- pooling + output head ----
    pool_kernel<<<cdiv((long long)N * 8, B), B>>>(bufA, batch, gmax, gsum, gcnt, N);
    out_kernel<<<cdiv(N_GRAPHS_C * 10, B), B>>>(gmax, gsum, gcnt, Wout, bout, (float*)d_out);
}

// round 12
// speedup vs baseline: 2.2685x; 1.1312x over previous
#include <cuda_runtime.h>
#include <cuda_fp16.h>

#define N_NODES_C 200000
#define N_EDGES_C 3200000
#define N_GRAPHS_C 1024
#define SCAN_B 256
#define MAX_BLOCKS_SCAN 1024

// ---------------- static device scratch (no allocs allowed) ----------------
__device__ __align__(16) float g_bufA[(size_t)N_NODES_C * 64];
__device__ __align__(16) float g_bufB[(size_t)N_NODES_C * 64];   // also used as half h1 table
__device__ __align__(16) float g_bufC[(size_t)N_NODES_C * 32];   // half t2 | half h3
__device__ __align__(16) float g_bufD[(size_t)N_NODES_C * 64];
__device__ __align__(16) int2  g_csr[N_EDGES_C];                 // {src, norm_bits}
__device__ __align__(16) int   g_deg[N_NODES_C];
__device__ __align__(16) int   g_incl[N_NODES_C];
__device__ __align__(16) int   g_rowstart[N_NODES_C];
__device__ __align__(16) int   g_cursor[N_NODES_C];
__device__ __align__(16) int   g_partials[MAX_BLOCKS_SCAN];
__device__ __align__(16) float g_dinv[N_NODES_C];
__device__ __align__(16) float g_gmax[N_GRAPHS_C * 32];
__device__ __align__(16) float g_gsum[N_GRAPHS_C * 32];
__device__ __align__(16) float g_gcnt[N_GRAPHS_C];

// ---------------- helpers ----------------
__device__ __forceinline__ void red_add_v4(float* addr, float4 v) {
    asm volatile("red.global.add.v4.f32 [%0], {%1, %2, %3, %4};"
                 :: "l"(addr), "f"(v.x), "f"(v.y), "f"(v.z), "f"(v.w)
                 : "memory");
}

__device__ __forceinline__ unsigned long long fma2(unsigned long long a,
                                                   unsigned long long b,
                                                   unsigned long long c) {
    unsigned long long d;
    asm("fma.rn.f32x2 %0, %1, %2, %3;" : "=l"(d) : "l"(a), "l"(b), "l"(c));
    return d;
}

__device__ __forceinline__ unsigned long long pack2(float x) {
    unsigned long long r;
    asm("mov.b64 %0, {%1, %1};" : "=l"(r) : "r"(__float_as_uint(x)));
    return r;
}

__device__ __forceinline__ float2 h2f(unsigned int u) {
    __half2 h = *reinterpret_cast<__half2*>(&u);
    return __half22float2(h);
}
__device__ __forceinline__ unsigned int f2h(float a, float b) {
    __half2 h = __floats2half2_rn(a, b);
    return *reinterpret_cast<unsigned int*>(&h);
}
__device__ __forceinline__ void fma8(float* acc, uint4 r, float n) {
    float2 p0 = h2f(r.x), p1 = h2f(r.y), p2 = h2f(r.z), p3 = h2f(r.w);
    acc[0] = fmaf(n, p0.x, acc[0]); acc[1] = fmaf(n, p0.y, acc[1]);
    acc[2] = fmaf(n, p1.x, acc[2]); acc[3] = fmaf(n, p1.y, acc[3]);
    acc[4] = fmaf(n, p2.x, acc[4]); acc[5] = fmaf(n, p2.y, acc[5]);
    acc[6] = fmaf(n, p3.x, acc[6]); acc[7] = fmaf(n, p3.y, acc[7]);
}

// ---------------- degree ----------------
__global__ void deg_kernel(const int* __restrict__ dst, int* __restrict__ deg, int E) {
    int t = blockIdx.x * blockDim.x + threadIdx.x;
    int e0 = t * 4;
    if (e0 >= E) return;
    if (e0 + 3 < E) {
        int4 d4 = *(const int4*)(dst + e0);
        atomicAdd(&deg[d4.x], 1);
        atomicAdd(&deg[d4.y], 1);
        atomicAdd(&deg[d4.z], 1);
        atomicAdd(&deg[d4.w], 1);
    } else {
        for (int k = 0; e0 + k < E; k++) atomicAdd(&deg[dst[e0 + k]], 1);
    }
}

__global__ void dinv_kernel(const int* __restrict__ deg, float* __restrict__ dinv, int N) {
    int i = blockIdx.x * blockDim.x + threadIdx.x;
    if (i < N) dinv[i] = rsqrtf((float)(deg[i] + 1));  // +1 self-loop
}

// ---------------- 3-phase exclusive scan of deg -> rowstart (+cursor copy) --------
__global__ void scan_block_kernel(const int* __restrict__ deg, int* __restrict__ incl,
                                  int* __restrict__ partials, int N) {
    __shared__ int sh[SCAN_B];
    int tid = threadIdx.x;
    int i = blockIdx.x * SCAN_B + tid;
    int v = (i < N) ? deg[i] : 0;
    sh[tid] = v;
    __syncthreads();
    #pragma unroll
    for (int off = 1; off < SCAN_B; off <<= 1) {
        int t = (tid >= off) ? sh[tid - off] : 0;
        __syncthreads();
        sh[tid] += t;
        __syncthreads();
    }
    if (i < N) incl[i] = sh[tid];
    if (tid == SCAN_B - 1) partials[blockIdx.x] = sh[tid];
}

__global__ void scan_partials_kernel(int* __restrict__ partials, int NB) {
    __shared__ int sh[MAX_BLOCKS_SCAN];
    int tid = threadIdx.x;
    sh[tid] = (tid < NB) ? partials[tid] : 0;
    __syncthreads();
    #pragma unroll
    for (int off = 1; off < MAX_BLOCKS_SCAN; off <<= 1) {
        int t = (tid >= off) ? sh[tid - off] : 0;
        __syncthreads();
        sh[tid] += t;
        __syncthreads();
    }
    if (tid < NB) partials[tid] = sh[tid];
}

__global__ void scan_final_kernel(const int* __restrict__ incl, const int* __restrict__ deg,
                                  const int* __restrict__ partials,
                                  int* __restrict__ rowstart, int* __restrict__ cursor, int N) {
    int i = blockIdx.x * SCAN_B + threadIdx.x;
    if (i >= N) return;
    int off = (blockIdx.x > 0) ? partials[blockIdx.x - 1] : 0;
    int rs = incl[i] - deg[i] + off;  // exclusive scan
    rowstart[i] = rs;
    cursor[i] = rs;
}

// ---------------- CSR fill: csr[pos] = {src, norm} grouped by dst ----------------
__global__ void fill_kernel(const int* __restrict__ src, const int* __restrict__ dst,
                            const float* __restrict__ dinv, int* __restrict__ cursor,
                            int2* __restrict__ csr, int E) {
    int e = blockIdx.x * blockDim.x + threadIdx.x;
    if (e >= E) return;
    int s = src[e];
    int d = dst[e];
    float nrm = dinv[s] * dinv[d];
    int pos = atomicAdd(&cursor[d], 1);
    csr[pos] = make_int2(s, __float_as_int(nrm));
}

// ---------------- fp32 gather (layer 0, C=8): chunk-parallel, 2 threads/node ------
__global__ void gather0_kernel(const float* __restrict__ t, float* __restrict__ agg,
                               const int2* __restrict__ csr, const int* __restrict__ rowstart,
                               const int* __restrict__ deg, const float* __restrict__ dinv, int N) {
    const int C = 8, TPN = 2;
    int gid = blockIdx.x * blockDim.x + threadIdx.x;
    int node = gid / TPN;
    int j = gid % TPN;
    if (node >= N) return;

    int start = rowstart[node];
    int cnt = deg[node];
    float di = dinv[node];
    float s2 = di * di;

    float4 self = *(const float4*)(t + (size_t)node * C + j * 4);
    float4 acc;
    acc.x = s2 * self.x; acc.y = s2 * self.y; acc.z = s2 * self.z; acc.w = s2 * self.w;

    int k = 0;
    for (; k + 2 <= cnt; k += 2) {
        int2 e0 = csr[start + k];
        int2 e1 = csr[start + k + 1];
        float4 v0 = *(const float4*)(t + (size_t)e0.x * C + j * 4);
        float4 v1 = *(const float4*)(t + (size_t)e1.x * C + j * 4);
        float n0 = __int_as_float(e0.y);
        float n1 = __int_as_float(e1.y);
        acc.x = fmaf(n0, v0.x, acc.x); acc.y = fmaf(n0, v0.y, acc.y);
        acc.z = fmaf(n0, v0.z, acc.z); acc.w = fmaf(n0, v0.w, acc.w);
        acc.x = fmaf(n1, v1.x, acc.x); acc.y = fmaf(n1, v1.y, acc.y);
        acc.z = fmaf(n1, v1.z, acc.z); acc.w = fmaf(n1, v1.w, acc.w);
    }
    if (k < cnt) {
        int2 e0 = csr[start + k];
        float4 v0 = *(const float4*)(t + (size_t)e0.x * C + j * 4);
        float n0 = __int_as_float(e0.y);
        acc.x = fmaf(n0, v0.x, acc.x); acc.y = fmaf(n0, v0.y, acc.y);
        acc.z = fmaf(n0, v0.z, acc.z); acc.w = fmaf(n0, v0.w, acc.w);
    }
    *(float4*)(agg + (size_t)node * C + j * 4) = acc;
}

// ---------------- half-input gather: C/8 threads per node, 4-way edge unroll ------
// acc = s2*self (+b) + sum nrm*row;  output fp32 (for GEMM) or relu->half (h3 table)
template<int C, bool ADDB, bool OUT_HALF_RELU>
__global__ void gatherH_kernel(const __half* __restrict__ t, void* __restrict__ outv,
                               const int2* __restrict__ csr, const int* __restrict__ rowstart,
                               const int* __restrict__ deg, const float* __restrict__ dinv,
                               const float* __restrict__ b, int N) {
    const int TPN = C / 8;
    int gid = blockIdx.x * blockDim.x + threadIdx.x;
    int node = gid / TPN;
    int j = gid % TPN;
    if (node >= N) return;

    int start = rowstart[node];
    int cnt = deg[node];
    float di = dinv[node];
    float s2 = di * di;

    const uint4* tv = (const uint4*)t;  // 8 halves per uint4; row stride C/8 uint4s
    uint4 sv = tv[(size_t)node * TPN + j];
    float acc[8];
    {
        float2 p0 = h2f(sv.x), p1 = h2f(sv.y), p2 = h2f(sv.z), p3 = h2f(sv.w);
        acc[0] = s2 * p0.x; acc[1] = s2 * p0.y;
        acc[2] = s2 * p1.x; acc[3] = s2 * p1.y;
        acc[4] = s2 * p2.x; acc[5] = s2 * p2.y;
        acc[6] = s2 * p3.x; acc[7] = s2 * p3.y;
    }
    if (ADDB) {
        float4 b0 = *(const float4*)(b + j * 8);
        float4 b1 = *(const float4*)(b + j * 8 + 4);
        acc[0] += b0.x; acc[1] += b0.y; acc[2] += b0.z; acc[3] += b0.w;
        acc[4] += b1.x; acc[5] += b1.y; acc[6] += b1.z; acc[7] += b1.w;
    }

    int k = 0;
    for (; k + 4 <= cnt; k += 4) {
        int2 e0 = csr[start + k];
        int2 e1 = csr[start + k + 1];
        int2 e2 = csr[start + k + 2];
        int2 e3 = csr[start + k + 3];
        uint4 r0 = tv[(size_t)e0.x * TPN + j];
        uint4 r1 = tv[(size_t)e1.x * TPN + j];
        uint4 r2 = tv[(size_t)e2.x * TPN + j];
        uint4 r3 = tv[(size_t)e3.x * TPN + j];
        fma8(acc, r0, __int_as_float(e0.y));
        fma8(acc, r1, __int_as_float(e1.y));
        fma8(acc, r2, __int_as_float(e2.y));
        fma8(acc, r3, __int_as_float(e3.y));
    }
    for (; k < cnt; k++) {
        int2 e0 = csr[start + k];
        uint4 r0 = tv[(size_t)e0.x * TPN + j];
        fma8(acc, r0, __int_as_float(e0.y));
    }

    if (OUT_HALF_RELU) {
        #pragma unroll
        for (int i = 0; i < 8; i++) acc[i] = fmaxf(acc[i], 0.f);
        uint4 o;
        o.x = f2h(acc[0], acc[1]); o.y = f2h(acc[2], acc[3]);
        o.z = f2h(acc[4], acc[5]); o.w = f2h(acc[6], acc[7]);
        ((uint4*)outv)[(size_t)node * TPN + j] = o;
    } else {
        float* out = (float*)outv;
        float4 o0 = make_float4(acc[0], acc[1], acc[2], acc[3]);
        float4 o1 = make_float4(acc[4], acc[5], acc[6], acc[7]);
        *(float4*)(out + (size_t)node * C + j * 8) = o0;
        *(float4*)(out + (size_t)node * C + j * 8 + 4) = o1;
    }
}

// ---------------- GEMM: out[i] = act(in[i] @ W (+ b)); optional half output -------
// ACT: 0=none, 1=tanh, 2=relu.  in != out.
template<int IN, int OUT, int ACT, bool HASB, bool OUTH>
__global__ void gemm_kernel(const float* __restrict__ in, const float* __restrict__ W,
                            const float* __restrict__ b, void* __restrict__ outv, int N) {
    __shared__ __align__(16) float Ws[IN * OUT];
    __shared__ __align__(16) float bs[OUT];
    for (int i = threadIdx.x; i < IN * OUT; i += blockDim.x) Ws[i] = W[i];
    if (HASB) for (int i = threadIdx.x; i < OUT; i += blockDim.x) bs[i] = b[i];
    __syncthreads();

    int node = blockIdx.x * blockDim.x + threadIdx.x;
    if (node >= N) return;
    const float* row = in + (size_t)node * IN;

    unsigned long long acc[OUT / 2];
    #pragma unroll
    for (int j = 0; j < OUT / 2; j++) {
        if (HASB) {
            float2 bb = *(const float2*)&bs[2 * j];
            unsigned long long p;
            asm("mov.b64 %0, {%1, %2};" : "=l"(p)
                : "r"(__float_as_uint(bb.x)), "r"(__float_as_uint(bb.y)));
            acc[j] = p;
        } else {
            acc[j] = 0ULL;
        }
    }

    #pragma unroll 4
    for (int k = 0; k < IN; k++) {
        unsigned long long xk2 = pack2(row[k]);
        const unsigned long long* wrow = (const unsigned long long*)&Ws[k * OUT];
        #pragma unroll
        for (int j = 0; j < OUT / 2; j++)
            acc[j] = fma2(xk2, wrow[j], acc[j]);
    }

    float* o = OUTH ? nullptr : ((float*)outv + (size_t)node * OUT);
    unsigned int* oh = OUTH ? ((unsigned int*)outv + (size_t)node * (OUT / 2)) : nullptr;
    #pragma unroll
    for (int j = 0; j < OUT / 2; j++) {
        float2 v;
        unsigned int lo, hi;
        asm("mov.b64 {%0, %1}, %2;" : "=r"(lo), "=r"(hi) : "l"(acc[j]));
        v.x = __uint_as_float(lo); v.y = __uint_as_float(hi);
        if (ACT == 1) { v.x = tanhf(v.x); v.y = tanhf(v.y); }
        if (ACT == 2) { v.x = fmaxf(v.x, 0.f); v.y = fmaxf(v.y, 0.f); }
        if (OUTH) oh[j] = f2h(v.x, v.y);
        else      *(float2*)(o + 2 * j) = v;
    }
}

// ---------------- pooling ----------------
__global__ void pool_kernel(const float* __restrict__ h, const int* __restrict__ batch,
                            float* __restrict__ gmax, float* __restrict__ gsum,
                            float* __restrict__ gcnt, int N) {
    int gid = blockIdx.x * blockDim.x + threadIdx.x;
    int node = gid / 8;
    int j = gid % 8;
    if (node >= N) return;
    float4 v = *(const float4*)(h + (size_t)node * 32 + j * 4);
    int g = batch[node];
    int base = g * 32 + j * 4;
    // h is post-ReLU (>=0) so int compare == float compare; gmax init = 0
    atomicMax((int*)gmax + base + 0, __float_as_int(v.x));
    atomicMax((int*)gmax + base + 1, __float_as_int(v.y));
    atomicMax((int*)gmax + base + 2, __float_as_int(v.z));
    atomicMax((int*)gmax + base + 3, __float_as_int(v.w));
    red_add_v4(gsum + base, v);
    if (j == 0) atomicAdd(&gcnt[g], 1.0f);
}

// ---------------- final linear ----------------
__global__ void out_kernel(const float* __restrict__ gmax, const float* __restrict__ gsum,
                           const float* __restrict__ gcnt, const float* __restrict__ Wout,
                           const float* __restrict__ bout, float* __restrict__ out) {
    int gid = blockIdx.x * blockDim.x + threadIdx.x;
    if (gid >= N_GRAPHS_C * 10) return;
    int g = gid / 10, o = gid % 10;
    float inv = 1.0f / fmaxf(gcnt[g], 1.0f);
    float acc = bout[o];
    #pragma unroll
    for (int k = 0; k < 32; k++) acc += gmax[g * 32 + k] * Wout[k * 10 + o];
    #pragma unroll
    for (int k = 0; k < 32; k++) acc += gsum[g * 32 + k] * inv * Wout[(32 + k) * 10 + o];
    out[gid] = acc;
}

// ---------------- launch ----------------
static inline int cdiv(long long a, int b) { return (int)((a + b - 1) / b); }

extern "C" void kernel_launch(void* const* d_in, const int* in_sizes, int n_in,
                              void* d_out, int out_size) {
    const float* x     = (const float*)d_in[0];
    const int*   ei    = (const int*)d_in[1];    // int32 (JAX x64 disabled)
    const int*   batch = (const int*)d_in[2];    // int32
    const float* W0 = (const float*)d_in[3];
    const float* b0 = (const float*)d_in[4];
    const float* W1 = (const float*)d_in[5];
    const float* b1 = (const float*)d_in[6];
    const float* W2 = (const float*)d_in[7];
    const float* b2 = (const float*)d_in[8];
    const float* W3 = (const float*)d_in[9];
    const float* b3 = (const float*)d_in[10];
    const float* Wout = (const float*)d_in[11];
    const float* bout = (const float*)d_in[12];

    int N = in_sizes[0] / 8;
    int E = in_sizes[1] / 2;
    const int* src = ei;
    const int* dst = ei + E;

    float *bufA, *bufB, *bufC, *bufD, *dinv, *gmax, *gsum, *gcnt;
    int *deg, *incl, *rowstart, *cursor, *partials; int2 *csr;
    cudaGetSymbolAddress((void**)&bufA, g_bufA);
    cudaGetSymbolAddress((void**)&bufB, g_bufB);
    cudaGetSymbolAddress((void**)&bufC, g_bufC);
    cudaGetSymbolAddress((void**)&bufD, g_bufD);
    cudaGetSymbolAddress((void**)&csr,  g_csr);
    cudaGetSymbolAddress((void**)&deg,  g_deg);
    cudaGetSymbolAddress((void**)&incl, g_incl);
    cudaGetSymbolAddress((void**)&rowstart, g_rowstart);
    cudaGetSymbolAddress((void**)&cursor,   g_cursor);
    cudaGetSymbolAddress((void**)&partials, g_partials);
    cudaGetSymbolAddress((void**)&dinv, g_dinv);
    cudaGetSymbolAddress((void**)&gmax, g_gmax);
    cudaGetSymbolAddress((void**)&gsum, g_gsum);
    cudaGetSymbolAddress((void**)&gcnt, g_gcnt);

    // half-table views
    __half* h1h = (__half*)bufB;                              // 200k x 64 halves (25.6MB)
    __half* t2h = (__half*)bufC;                              // 200k x 32 halves
    __half* h3h = (__half*)bufC + (size_t)N_NODES_C * 32;     // 200k x 32 halves

    const int B = 256;
    int NB = cdiv(N, SCAN_B);  // 782 <= 1024

    cudaMemsetAsync(deg,  0, (size_t)N * sizeof(int));
    cudaMemsetAsync(gmax, 0, (size_t)N_GRAPHS_C * 32 * sizeof(float));
    cudaMemsetAsync(gsum, 0, (size_t)N_GRAPHS_C * 32 * sizeof(float));
    cudaMemsetAsync(gcnt, 0, (size_t)N_GRAPHS_C * sizeof(float));

    // ---- graph preprocessing: deg, dinv, CSR ----
    deg_kernel<<<cdiv(cdiv(E, 4), B), B>>>(dst, deg, E);
    dinv_kernel<<<cdiv(N, B), B>>>(deg, dinv, N);
    scan_block_kernel<<<NB, SCAN_B>>>(deg, incl, partials, N);
    scan_partials_kernel<<<1, MAX_BLOCKS_SCAN>>>(partials, NB);
    scan_final_kernel<<<NB, SCAN_B>>>(incl, deg, partials, rowstart, cursor, N);
    fill_kernel<<<cdiv(E, B), B>>>(src, dst, dinv, cursor, csr, E);

    // ---- layer 0: aggregate at C=8 fp32, then 8->64 tanh -> half h1 ----
    gather0_kernel<<<cdiv((long long)N * 2, B), B>>>(x, bufA, csr, rowstart, deg, dinv, N);
    gemm_kernel<8, 64, 1, true, true><<<cdiv(N, B), B>>>(bufA, W0, b0, h1h, N);

    // ---- layer 1: half gather C=64 -> fp32 agg1, 64->64 relu -> fp32 h2 ----
    gatherH_kernel<64, false, false><<<cdiv((long long)N * 8, B), B>>>(h1h, bufD, csr, rowstart, deg, dinv, nullptr, N);
    gemm_kernel<64, 64, 2, true, false><<<cdiv(N, B), B>>>(bufD, W1, b1, bufA, N);

    // ---- layer 2: GEMM first (64->32, no bias) -> half t2; gather(+b2, relu) -> half h3 ----
    gemm_kernel<64, 32, 0, false, true><<<cdiv(N, B), B>>>(bufA, W2, nullptr, t2h, N);
    gatherH_kernel<32, true, true><<<cdiv((long long)N * 4, B), B>>>(t2h, h3h, csr, rowstart, deg, dinv, b2, N);

    // ---- layer 3: half gather C=32 -> fp32 agg3, 32->32 relu -> h4 ----
    gatherH_kernel<32, false, false><<<cdiv((long long)N * 4, B), B>>>(h3h, bufD, csr, rowstart, deg, dinv, nullptr, N);
    gemm_kernel<32, 32, 2, true, false><<<cdiv(N, B), B>>>(bufD, W3, b3, bufA, N);

    // ---- pooling + output head ----
    pool_kernel<<<cdiv((long long)N * 8, B), B>>>(bufA, batch, gmax, gsum, gcnt, N);
    out_kernel<<<cdiv(N_GRAPHS_C * 10, B), B>>>(gmax, gsum, gcnt, Wout, bout, (float*)d_out);
}